// round 2
// baseline (speedup 1.0000x reference)
#include <cuda_runtime.h>
#include <cstddef>

#define NB 8
#define NH 96
#define NW 96
#define NC 512
#define NCQ 64
#define NT (NB*NH*NW)   // 73728 tokens

// ---------------- scratch (device globals; no runtime allocation) --------
__device__ float g_q[(size_t)NT*NCQ];          // [t][64]
__device__ float g_k[(size_t)NT*NCQ];          // [t][64]
__device__ float g_v[(size_t)NT*NC];           // [t][512]
__device__ float g_sv[(size_t)NB*NW*NH*NH];    // [b][w][h][g] logits/probs
__device__ float g_sh[(size_t)NT*NW];          // [b][h][w][u] logits/probs
__device__ float g_yv[(size_t)NT*NC];          // [t][512]

// =========================================================================
// GEMM: C[M,N] = A[M,K] @ B[K,N] + bias[N].  M%128==0, N%64==0, K%16==0.
// BM=128, BN=64, BK=16, 256 threads, 8x4 microtile per thread.
// dst: 0 -> g_q, 1 -> g_k, 2 -> g_v
// =========================================================================
__global__ __launch_bounds__(256) void gemm_bias_kernel(
    const float* __restrict__ A, const float* __restrict__ Bw,
    const float* __restrict__ bias, int dst, int N, int K)
{
    __shared__ float4 As4[512];   // [m][k4]: 128 rows x 4 float4 (16 floats)
    __shared__ float4 Bs4[256];   // [k][n4]: 16 rows x 16 float4 (64 floats)

    float* __restrict__ C = (dst == 0) ? g_q : (dst == 1) ? g_k : g_v;

    const int tid = threadIdx.x;
    const int tx = tid & 15;          // n direction, 16
    const int ty = tid >> 4;          // m direction, 16
    const size_t bm = (size_t)blockIdx.x * 128;
    const int bn = blockIdx.y * 64;

    float acc[8][4];
    #pragma unroll
    for (int i = 0; i < 8; i++) { acc[i][0]=0.f; acc[i][1]=0.f; acc[i][2]=0.f; acc[i][3]=0.f; }

    for (int k0 = 0; k0 < K; k0 += 16) {
        // A tile: 128x16 floats = 512 float4, two per thread (linear -> conflict free)
        int idx = tid;
        #pragma unroll
        for (int it = 0; it < 2; it++, idx += 256) {
            int m = idx >> 2, k4 = idx & 3;
            As4[idx] = *(const float4*)(A + (bm + m) * K + k0 + k4 * 4);
        }
        // B tile: 16x64 floats = 256 float4, one per thread
        {
            int r = tid >> 4, c4 = tid & 15;
            Bs4[tid] = *(const float4*)(Bw + (size_t)(k0 + r) * N + bn + c4 * 4);
        }
        __syncthreads();

        const float* As = (const float*)As4;
        #pragma unroll
        for (int kk = 0; kk < 16; kk++) {
            float4 bv = Bs4[kk * 16 + tx];           // LDS.128, conflict-free
            #pragma unroll
            for (int i = 0; i < 8; i++) {
                float a = As[(ty * 8 + i) * 16 + kk]; // broadcast across tx
                acc[i][0] += a * bv.x;
                acc[i][1] += a * bv.y;
                acc[i][2] += a * bv.z;
                acc[i][3] += a * bv.w;
            }
        }
        __syncthreads();
    }

    float4 bb = *(const float4*)(bias + bn + tx * 4);
    #pragma unroll
    for (int i = 0; i < 8; i++) {
        size_t m = bm + ty * 8 + i;
        float4 o;
        o.x = acc[i][0] + bb.x; o.y = acc[i][1] + bb.y;
        o.z = acc[i][2] + bb.z; o.w = acc[i][3] + bb.w;
        *(float4*)(C + m * N + bn + tx * 4) = o;
    }
}

// =========================================================================
// Logits: per block, S[96][96] = Qrows(96x64) @ Krows(96x64)^T.
// mode 0: vertical (per (b,w) column, strided rows, diag masked) -> g_sv
// mode 1: horizontal (per (b,h) row, contiguous rows)            -> g_sh
// =========================================================================
__global__ __launch_bounds__(256) void logits_kernel(int mode)
{
    __shared__ float Qs[96][17];   // 16-wide k chunk, +1 pad
    __shared__ float Ks[96][17];

    const int tid = threadIdx.x;
    const int tx = tid & 15, ty = tid >> 4;
    const int bid = blockIdx.x;

    size_t base; int stride;
    if (mode == 0) {
        int b = bid / NW, w = bid % NW;
        base = ((size_t)b * NH * NW + w) * NCQ;   // q[b,0,w,:]
        stride = NW * NCQ;                        // step h
    } else {
        base = (size_t)bid * NW * NCQ;            // q[b,h,0,:]
        stride = NCQ;                             // step u/w
    }
    float* __restrict__ out = (mode == 0 ? g_sv : g_sh) + (size_t)bid * 96 * 96;

    float acc[6][6];
    #pragma unroll
    for (int i = 0; i < 6; i++)
        #pragma unroll
        for (int j = 0; j < 6; j++) acc[i][j] = 0.f;

    for (int kc = 0; kc < NCQ; kc += 16) {
        for (int idx = tid; idx < 96 * 16; idx += 256) {
            int r = idx >> 4, c = idx & 15;
            size_t ga = base + (size_t)r * stride + kc + c;
            Qs[r][c] = g_q[ga];
            Ks[r][c] = g_k[ga];
        }
        __syncthreads();
        #pragma unroll
        for (int kk = 0; kk < 16; kk++) {
            float a[6], bv[6];
            #pragma unroll
            for (int i = 0; i < 6; i++) a[i] = Qs[ty * 6 + i][kk];
            #pragma unroll
            for (int j = 0; j < 6; j++) bv[j] = Ks[tx * 6 + j][kk];
            #pragma unroll
            for (int i = 0; i < 6; i++)
                #pragma unroll
                for (int j = 0; j < 6; j++) acc[i][j] += a[i] * bv[j];
        }
        __syncthreads();
    }

    #pragma unroll
    for (int i = 0; i < 6; i++) {
        int h = ty * 6 + i;
        #pragma unroll
        for (int j = 0; j < 6; j++) {
            int g = tx * 6 + j;
            float v = acc[i][j];
            if (mode == 0 && h == g) v = -1e30f;   // mask diagonal (vertical self)
            out[h * 96 + g] = v;
        }
    }
}

// =========================================================================
// Softmax over the 192 concatenated logits per token; in place.
// One warp per token; 96 = 3*32 per half.
// =========================================================================
__global__ void softmax_kernel()
{
    int gw = (int)((blockIdx.x * blockDim.x + threadIdx.x) >> 5);
    int lane = threadIdx.x & 31;
    if (gw >= NT) return;
    int b = gw / (NH * NW), rem = gw % (NH * NW);
    int h = rem / NW, w = rem % NW;

    float* __restrict__ svp = g_sv + (((size_t)b * NW + w) * NH + h) * NH;  // 96 (over g)
    float* __restrict__ shp = g_sh + (size_t)gw * NW;                        // 96 (over u)

    float v[6];
    float m = -3.4e38f;
    #pragma unroll
    for (int i = 0; i < 3; i++) { v[i]     = svp[lane + 32 * i]; m = fmaxf(m, v[i]); }
    #pragma unroll
    for (int i = 0; i < 3; i++) { v[3 + i] = shp[lane + 32 * i]; m = fmaxf(m, v[3 + i]); }
    #pragma unroll
    for (int o = 16; o; o >>= 1) m = fmaxf(m, __shfl_xor_sync(0xffffffffu, m, o));

    float s = 0.f;
    #pragma unroll
    for (int i = 0; i < 6; i++) { v[i] = __expf(v[i] - m); s += v[i]; }
    #pragma unroll
    for (int o = 16; o; o >>= 1) s += __shfl_xor_sync(0xffffffffu, s, o);
    float inv = 1.0f / s;

    #pragma unroll
    for (int i = 0; i < 3; i++) svp[lane + 32 * i] = v[i] * inv;
    #pragma unroll
    for (int i = 0; i < 3; i++) shp[lane + 32 * i] = v[3 + i] * inv;
}

// =========================================================================
// PV: per block Y(96x512) = P(96x96) @ V(96x512).
// mode 0: vertical   (P=av per (b,w), V rows strided)  -> g_yv
// mode 1: horizontal (P=ah per (b,h), V rows contig)   -> out = x + gamma*(yv+yh)
// =========================================================================
__global__ __launch_bounds__(256) void pv_kernel(
    const float* __restrict__ x, const float* __restrict__ gamma_p,
    float* __restrict__ out, int mode)
{
    __shared__ float Ps[96 * 96];   // 36,864 B
    __shared__ float4 Vs4[256];     // 16 k-rows x 64 cols = 4,096 B

    const int tid = threadIdx.x;
    const int tx = tid & 15, ty = tid >> 4;
    const int bid = blockIdx.x;

    const float* __restrict__ Pb = (mode == 0 ? g_sv : g_sh) + (size_t)bid * 96 * 96;
    size_t vrow0; int vstride;
    if (mode == 0) {
        int b = bid / NW, w = bid % NW;
        vrow0 = ((size_t)b * NH * NW + w) * NC;  // v[b,0,w,:]; also yv row base
        vstride = NW * NC;                        // step g / h
    } else {
        vrow0 = (size_t)bid * NW * NC;            // v[b,h,0,:]; also out row base
        vstride = NC;                             // step u / w
    }

    for (int idx = tid; idx < 96 * 96; idx += 256) Ps[idx] = Pb[idx];
    float gam = (mode == 1) ? *gamma_p : 0.f;

    for (int nc = 0; nc < NC; nc += 64) {
        float acc[6][4];
        #pragma unroll
        for (int i = 0; i < 6; i++) { acc[i][0]=0.f; acc[i][1]=0.f; acc[i][2]=0.f; acc[i][3]=0.f; }

        for (int kc = 0; kc < 96; kc += 16) {
            __syncthreads();   // protect Vs4 (and Ps on first pass)
            {
                int r = tid >> 4, c4 = tid & 15;
                Vs4[tid] = *(const float4*)(g_v + vrow0 + (size_t)(kc + r) * vstride + nc + c4 * 4);
            }
            __syncthreads();
            #pragma unroll
            for (int kk = 0; kk < 16; kk++) {
                float4 bv = Vs4[kk * 16 + tx];
                #pragma unroll
                for (int i = 0; i < 6; i++) {
                    float a = Ps[(ty * 6 + i) * 96 + kc + kk];  // broadcast
                    acc[i][0] += a * bv.x;
                    acc[i][1] += a * bv.y;
                    acc[i][2] += a * bv.z;
                    acc[i][3] += a * bv.w;
                }
            }
        }

        #pragma unroll
        for (int i = 0; i < 6; i++) {
            int m = ty * 6 + i;
            size_t oidx = vrow0 + (size_t)m * vstride + nc + tx * 4;
            if (mode == 0) {
                float4 o; o.x = acc[i][0]; o.y = acc[i][1]; o.z = acc[i][2]; o.w = acc[i][3];
                *(float4*)(g_yv + oidx) = o;
            } else {
                float4 yv = *(const float4*)(g_yv + oidx);
                float4 xx = *(const float4*)(x + oidx);
                float4 o;
                o.x = xx.x + gam * (yv.x + acc[i][0]);
                o.y = xx.y + gam * (yv.y + acc[i][1]);
                o.z = xx.z + gam * (yv.z + acc[i][2]);
                o.w = xx.w + gam * (yv.w + acc[i][3]);
                *(float4*)(out + oidx) = o;
            }
        }
    }
}

// =========================================================================
extern "C" void kernel_launch(void* const* d_in, const int* in_sizes, int n_in,
                              void* d_out, int out_size)
{
    const float* x     = (const float*)d_in[0];
    const float* Wq    = (const float*)d_in[1];
    const float* bq    = (const float*)d_in[2];
    const float* Wk    = (const float*)d_in[3];
    const float* bk    = (const float*)d_in[4];
    const float* Wv    = (const float*)d_in[5];
    const float* bv    = (const float*)d_in[6];
    const float* gamma = (const float*)d_in[7];
    float* out = (float*)d_out;
    (void)in_sizes; (void)n_in; (void)out_size;

    // Projections: M = 73728 (= 576*128)
    dim3 gqk(576, 1);
    gemm_bias_kernel<<<gqk, 256>>>(x, Wq, bq, 0, NCQ, NC);
    gemm_bias_kernel<<<gqk, 256>>>(x, Wk, bk, 1, NCQ, NC);
    dim3 gv(576, 8);
    gemm_bias_kernel<<<gv, 256>>>(x, Wv, bv, 2, NC, NC);

    // Logits
    logits_kernel<<<NB * NW, 256>>>(0);   // vertical (masked diag)
    logits_kernel<<<NB * NH, 256>>>(1);   // horizontal

    // Joint softmax over 192 logits per token (warp per token)
    softmax_kernel<<<NT / 8, 256>>>();

    // Attention-value + epilogue
    pv_kernel<<<NB * NW, 256>>>(x, gamma, out, 0);   // yv
    pv_kernel<<<NB * NH, 256>>>(x, gamma, out, 1);   // yh + gamma + residual
}